// round 16
// baseline (speedup 1.0000x reference)
#include <cuda_runtime.h>
#include <cuda_fp16.h>
typedef unsigned int u32; typedef unsigned long long u64; typedef unsigned short u16;

#define HWp 4096
#define Cc  256
#define Dd  256
#define ZQ_SIZE (8*256*4096)
#define DIFF_OFF ZQ_SIZE
#define IND_OFF (ZQ_SIZE+1)
#define DELTA 0.05f

// ---- device scratch ----
__device__ uint4 g_Af[256*4096];   // A hi frags: per tile t: 4096 uint4 (64KB)
__device__ u64   g_Bh[8*8192];     // B hi frags: per chunk nc: 8192 u64 (64KB)
__device__ float g_zt[32768*256];  // fp32 z, pixel-major
__device__ u16   g_cd[32768*32];   // candidate lists (32/pixel)
__device__ int   g_ct[32768];      // candidate counts

__device__ __forceinline__ u32 smem_u32(const void* p){u32 a;asm("{ .reg .u64 t; cvta.to.shared.u64 t, %1; cvt.u32.u64 %0, t; }":"=r"(a):"l"(p));return a;}
__device__ __forceinline__ u32 ordu(float v){u32 u=__float_as_uint(v);return (u&0x80000000u)?~u:(u|0x80000000u);}
__device__ __forceinline__ float unord(u32 u){return (u&0x80000000u)?__uint_as_float(u^0x80000000u):__uint_as_float(~u);}
__device__ __forceinline__ void hmma(float* c,const u32* a,const u32* b){
  asm volatile("mma.sync.aligned.m16n8k16.row.col.f32.f16.f16.f32 {%0,%1,%2,%3}, {%4,%5,%6,%7}, {%8,%9}, {%0,%1,%2,%3};"
    : "+f"(c[0]),"+f"(c[1]),"+f"(c[2]),"+f"(c[3])
    : "r"(a[0]),"r"(a[1]),"r"(a[2]),"r"(a[3]),"r"(b[0]),"r"(b[1]));
}
__device__ __forceinline__ void cpa16(u32 dst,const void* src){
  asm volatile("cp.async.cg.shared.global [%0], [%1], 16;"::"r"(dst),"l"(src):"memory");
}
#define CPA_COMMIT() asm volatile("cp.async.commit_group;":::"memory")
#define CPA_WAIT1()  asm volatile("cp.async.wait_group 1;":::"memory")
#define CPA_WAIT0()  asm volatile("cp.async.wait_group 0;":::"memory")

__device__ __forceinline__ u16 h16(float v){__half h=__float2half_rn(v);return *(u16*)&h;}

// exact fp32 warp dot: zv[8] per lane vs pw row n; deterministic xor-tree reduce
__device__ __forceinline__ float wdot(const float* zv,const float* __restrict__ pw,int n){
  const float* wr=pw+(size_t)n*Cc+(threadIdx.x&31)*8;
  float4 w0=*(const float4*)wr, w1=*(const float4*)(wr+4);
  float s=zv[0]*w0.x;
  s=fmaf(zv[1],w0.y,s); s=fmaf(zv[2],w0.z,s); s=fmaf(zv[3],w0.w,s);
  s=fmaf(zv[4],w1.x,s); s=fmaf(zv[5],w1.y,s); s=fmaf(zv[6],w1.z,s); s=fmaf(zv[7],w1.w,s);
  #pragma unroll
  for(int o=16;o>=1;o>>=1) s+=__shfl_xor_sync(0xffffffffu,s,o);
  return s;
}

// ===================== K1 (R8 verbatim) =====================
extern __shared__ float k1s[];
__global__ __launch_bounds__(256,1) void k1(const float* __restrict__ z,const float* __restrict__ pw){
  int tid=threadIdx.x, t=blockIdx.x;
  if(t<256){
    int pix0=t*128, b=pix0>>12, hw0=pix0&4095;
    const float* zb=z+(size_t)b*Cc*HWp+hw0;
    #pragma unroll
    for(int i=0;i<32;i++){
      int e4=tid+i*256; int c=e4>>5; int p4=(e4&31)<<2;
      float4 v=*(const float4*)(zb+(size_t)c*HWp+p4);
      float* d=k1s+c*129+p4;
      d[0]=v.x; d[1]=v.y; d[2]=v.z; d[3]=v.w;
    }
    __syncthreads();
    #pragma unroll 8
    for(int i=0;i<128;i++) g_zt[(size_t)(pix0+i)*Cc+tid]=k1s[tid*129+i];
    uint4* Ah=g_Af+(size_t)t*4096;
    #pragma unroll
    for(int i=0;i<16;i++){
      int u=tid+i*256;
      int lane=u&31, ks=(u>>5)&15, mt=u>>9;
      int r0=mt*16+(lane>>2);
      int c0=ks*16+((lane&3)<<1);
      u16 h0=h16(k1s[(c0  )*129+r0  ]*64.f), h1=h16(k1s[(c0+1)*129+r0  ]*64.f);
      u16 h2=h16(k1s[(c0  )*129+r0+8]*64.f), h3=h16(k1s[(c0+1)*129+r0+8]*64.f);
      u16 h4=h16(k1s[(c0+8)*129+r0  ]*64.f), h5=h16(k1s[(c0+9)*129+r0  ]*64.f);
      u16 h6=h16(k1s[(c0+8)*129+r0+8]*64.f), h7=h16(k1s[(c0+9)*129+r0+8]*64.f);
      uint4 H;
      H.x=h0|((u32)h1<<16); H.y=h2|((u32)h3<<16); H.z=h4|((u32)h5<<16); H.w=h6|((u32)h7<<16);
      Ah[u]=H;
    }
  } else {
    int base=(t-256)*2048;
    #pragma unroll
    for(int i=0;i<8;i++){
      int u=base+tid+i*256;
      int lane=u&31;
      int ks=(u>>5)&15;
      int nt=(u>>9)&15;
      int chunk=u>>13;
      int n=chunk*128+nt*8+(lane>>2);
      int k0=ks*16+((lane&3)<<1);
      const float* sp=pw+(size_t)n*Cc;
      u16 h0=h16(sp[k0  ]*32.f), h1=h16(sp[k0+1]*32.f);
      u16 h2=h16(sp[k0+8]*32.f), h3=h16(sp[k0+9]*32.f);
      g_Bh[(size_t)chunk*8192 + (nt*16+ks)*32 + lane]
        = (u64)(h0|((u32)h1<<16)) | ((u64)(h2|((u32)h3<<16))<<32);
    }
  }
}

// ===================== K2a: MMA loop + candidates (R8 loop verbatim) =====================
extern __shared__ char k2s[];
__global__ __launch_bounds__(512,1) void k2a(const float* __restrict__ pb,float* __restrict__ out){
  __shared__ u32 s_best[128];
  __shared__ float s_pb[1024];
  __shared__ int s_cnt[128];
  __shared__ u16 s_cand[128][32];
  int tid=threadIdx.x, lane=tid&31, warp=tid>>5, mw=warp&3, nw=warp>>2, t=blockIdx.x;
  int pix0=t*128;
  char* sm=k2s;
  u32 smb=smem_u32(k2s);

  { const uint4* src=g_Af+(size_t)t*4096; uint4* dst=(uint4*)sm;
    #pragma unroll
    for(int i=0;i<8;i++) dst[tid+i*512]=src[tid+i*512]; }
  for(int i=tid;i<1024;i+=512) s_pb[i]=pb[i];
  if(tid<128){ s_best[tid]=0u; s_cnt[tid]=0; }
  __syncthreads();

  #pragma unroll
  for(int c2=0;c2<2;c2++){
    u32 d=smb+65536+c2*65536;
    const char* s=(const char*)g_Bh+(size_t)c2*65536;
    #pragma unroll
    for(int j2=0;j2<8;j2++){int e=tid+j2*512; cpa16(d+e*16,s+(size_t)e*16);}
    CPA_COMMIT();
  }

  float bestV[4], secV[4]; int bestI[4];
  #pragma unroll
  for(int i=0;i<4;i++){bestV[i]=-3.4e38f;secV[i]=-3.4e38f;bestI[i]=0;}
  const float inv=4.8828125e-4f;
  const uint4* Ahp=(const uint4*)sm;

  for(int nc=0;nc<8;nc++){
    CPA_WAIT1();
    __syncthreads();
    const char* Bst=sm+65536+(nc&1)*65536;
    float C[2][4][4];
    #pragma unroll
    for(int i=0;i<2;i++)
      #pragma unroll
      for(int j=0;j<4;j++)
        #pragma unroll
        for(int c=0;c<4;c++) C[i][j][c]=0.f;

    #pragma unroll
    for(int ks=0;ks<16;ks++){
      u32 ah[2][4];
      #pragma unroll
      for(int i=0;i<2;i++){
        uint4 va=Ahp[((mw*2+i)*16+ks)*32+lane];
        ah[i][0]=va.x; ah[i][1]=va.y; ah[i][2]=va.z; ah[i][3]=va.w;
      }
      u32 bh[4][2];
      #pragma unroll
      for(int j=0;j<4;j++){
        int nt=nw*4+j;
        uint2 vh=*(const uint2*)(Bst+(size_t)((nt*16+ks)*32+lane)*8);
        bh[j][0]=vh.x; bh[j][1]=vh.y;
      }
      #pragma unroll
      for(int i=0;i<2;i++)
        #pragma unroll
        for(int j=0;j<4;j++)
          hmma(C[i][j],ah[i],bh[j]);
    }

    int nb=nc*128+nw*32+((lane&3)<<1);
    #pragma unroll
    for(int i=0;i<2;i++)
      #pragma unroll
      for(int rr=0;rr<2;rr++){
        int r=i*2+rr;
        #pragma unroll
        for(int j=0;j<4;j++)
          #pragma unroll
          for(int cc=0;cc<2;cc++){
            int n=nb+j*8+cc;
            float val=C[i][j][rr*2+cc]*inv+s_pb[n];
            if(val>bestV[r]){secV[r]=bestV[r];bestV[r]=val;bestI[r]=n;}
            else if(val>secV[r]) secV[r]=val;
          }
      }
    __syncthreads();
    if(nc+2<8){
      u32 d=smb+65536+(nc&1)*65536;
      const char* s=(const char*)g_Bh+(size_t)(nc+2)*65536;
      #pragma unroll
      for(int j2=0;j2<8;j2++){int e=tid+j2*512; cpa16(d+e*16,s+(size_t)e*16);}
    }
    CPA_COMMIT();
  }
  CPA_WAIT0();

  #pragma unroll
  for(int i=0;i<2;i++)
    #pragma unroll
    for(int rr=0;rr<2;rr++){
      int row=mw*32+i*16+rr*8+(lane>>2);
      atomicMax(&s_best[row],ordu(bestV[i*2+rr]));
    }
  __syncthreads();

  #pragma unroll
  for(int i=0;i<2;i++)
    #pragma unroll
    for(int rr=0;rr<2;rr++){
      int r=i*2+rr;
      int row=mw*32+i*16+rr*8+(lane>>2);
      float thr=unord(s_best[row])-DELTA;
      if(bestV[r]>=thr){
        int slot=atomicAdd(&s_cnt[row],1);
        s_cand[row][slot]=(u16)bestI[r];
      }
      if(secV[r]>=thr){
        int slot=atomicAdd(&s_cnt[row],1);
        s_cand[row][slot]=(u16)(0x8000u|((u32)nw<<2)|(u32)(lane&3));
      }
    }
  __syncthreads();

  // dump candidates to global
  if(tid<128) g_ct[pix0+tid]=s_cnt[tid];
  { const u32* srcc=(const u32*)s_cand;
    u32* dstc=(u32*)(g_cd+(size_t)pix0*32);
    for(int i=tid;i<2048;i+=512) dstc[i]=srcc[i];
  }
  if(t==0&&tid==0) out[DIFF_OFF]=0.0f;
}

// ===================== K2b: rescore + gather epilogue (R8 tail verbatim) =====================
__global__ __launch_bounds__(512,1) void k2b(const float* __restrict__ pw,const float* __restrict__ pb,
                                             const float* __restrict__ emb,float* __restrict__ out){
  __shared__ float s_pb[1024];
  __shared__ int s_idx[128];
  int tid=threadIdx.x, lane=tid&31, warp=tid>>5, t=blockIdx.x;
  int pix0=t*128, b=pix0>>12, hw0=pix0&4095;
  char* sm=k2s;

  for(int i=tid;i<1024;i+=512) s_pb[i]=pb[i];
  __syncthreads();

  // exact rescore: one warp per pixel
  for(int p=warp;p<128;p+=16){
    const float* zr=g_zt+(size_t)(pix0+p)*Cc+lane*8;
    float4 z0=*(const float4*)zr, z1=*(const float4*)(zr+4);
    float zv[8]={z0.x,z0.y,z0.z,z0.w,z1.x,z1.y,z1.z,z1.w};
    float bv=-3.4e38f; int bi=1024;
    int cnt=g_ct[pix0+p];
    const u16* cd=g_cd+(size_t)(pix0+p)*32;
    for(int e=0;e<cnt;e++){
      u32 ent=cd[e];
      if(ent<0x8000u){
        int n=(int)ent;
        float v=wdot(zv,pw,n)+s_pb[n];
        if(v>bv||(v==bv&&n<bi)){bv=v;bi=n;}
      }else{
        int nwm=(int)((ent>>2)&3), q=(int)(ent&3);
        for(int nc2=0;nc2<8;nc2++)
          for(int j=0;j<4;j++)
            #pragma unroll
            for(int cc=0;cc<2;cc++){
              int n=nc2*128+nwm*32+j*8+q*2+cc;
              float v=wdot(zv,pw,n)+s_pb[n];
              if(v>bv||(v==bv&&n<bi)){bv=v;bi=n;}
            }
      }
    }
    if(lane==0){ s_idx[p]=bi; out[IND_OFF+pix0+p]=(float)bi; }
  }
  __syncthreads();

  // gather epilogue
  float* gs2=(float*)sm;           // [128][257] = 131584B
  for(int i=tid;i<8192;i+=512){
    int p=i>>6; int d4=(i&63)<<2;
    float4 v=*(const float4*)(emb+(size_t)s_idx[p]*Dd+d4);
    float* d=gs2+p*257+d4;
    d[0]=v.x; d[1]=v.y; d[2]=v.z; d[3]=v.w;
  }
  __syncthreads();
  float* outz=out+(size_t)b*Dd*HWp+hw0;
  for(int i=tid;i<32768;i+=512){
    int d=i>>7, p=i&127;
    outz[(size_t)d*HWp+p]=gs2[p*257+d];
  }
}

extern "C" void kernel_launch(void* const* d_in, const int* in_sizes, int n_in,
                              void* d_out, int out_size)
{
  const float* z  =(const float*)d_in[0];
  const float* pw =(const float*)d_in[1];
  const float* pb =(const float*)d_in[2];
  const float* emb=(const float*)d_in[3];
  float* out=(float*)d_out;
  cudaFuncSetAttribute(k1, cudaFuncAttributeMaxDynamicSharedMemorySize,132096);
  cudaFuncSetAttribute(k2a,cudaFuncAttributeMaxDynamicSharedMemorySize,196608);
  cudaFuncSetAttribute(k2b,cudaFuncAttributeMaxDynamicSharedMemorySize,131584);
  k1 <<<288,256,132096>>>(z,pw);
  k2a<<<256,512,196608>>>(pb,out);
  k2b<<<256,512,131584>>>(pw,pb,emb,out);
}

// round 17
// speedup vs baseline: 1.1659x; 1.1659x over previous
#include <cuda_runtime.h>
#include <cuda_fp16.h>
typedef unsigned int u32; typedef unsigned long long u64; typedef unsigned short u16;

#define HWp 4096
#define Cc  256
#define Dd  256
#define ZQ_SIZE (8*256*4096)
#define DIFF_OFF ZQ_SIZE
#define IND_OFF (ZQ_SIZE+1)
#define DELTA 0.015f

// ---- device scratch ----
__device__ uint4 g_Af[256*4096];   // A hi frags: per tile t: 4096 uint4 (64KB)
__device__ u64   g_Bh[8*8192];     // B hi frags: per chunk nc: 8192 u64 (64KB)
__device__ float g_zt[32768*256];  // fp32 z, pixel-major

__device__ __forceinline__ u32 smem_u32(const void* p){u32 a;asm("{ .reg .u64 t; cvta.to.shared.u64 t, %1; cvt.u32.u64 %0, t; }":"=r"(a):"l"(p));return a;}
__device__ __forceinline__ u32 ordu(float v){u32 u=__float_as_uint(v);return (u&0x80000000u)?~u:(u|0x80000000u);}
__device__ __forceinline__ float unord(u32 u){return (u&0x80000000u)?__uint_as_float(u^0x80000000u):__uint_as_float(~u);}
__device__ __forceinline__ void hmma(float* c,const u32* a,const u32* b){
  asm volatile("mma.sync.aligned.m16n8k16.row.col.f32.f16.f16.f32 {%0,%1,%2,%3}, {%4,%5,%6,%7}, {%8,%9}, {%0,%1,%2,%3};"
    : "+f"(c[0]),"+f"(c[1]),"+f"(c[2]),"+f"(c[3])
    : "r"(a[0]),"r"(a[1]),"r"(a[2]),"r"(a[3]),"r"(b[0]),"r"(b[1]));
}
__device__ __forceinline__ void cpa16(u32 dst,const void* src){
  asm volatile("cp.async.cg.shared.global [%0], [%1], 16;"::"r"(dst),"l"(src):"memory");
}
#define CPA_COMMIT() asm volatile("cp.async.commit_group;":::"memory")
#define CPA_WAIT1()  asm volatile("cp.async.wait_group 1;":::"memory")
#define CPA_WAIT0()  asm volatile("cp.async.wait_group 0;":::"memory")

__device__ __forceinline__ u16 h16(float v){__half h=__float2half_rn(v);return *(u16*)&h;}

// exact fp32 16-lane dot: z regs (16 floats/lane) vs pw row n; deterministic xor-tree
// mask must be the caller's half-warp mask; shfl offsets <=8 stay inside the half.
__device__ __forceinline__ float wdot16(float4 z0,float4 z1,float4 z2,float4 z3,
                                        const float* __restrict__ pw,int n,int hl,u32 mask){
  const float* wr=pw+(size_t)n*Cc+hl*16;
  float4 w0=*(const float4*)wr, w1=*(const float4*)(wr+4);
  float4 w2=*(const float4*)(wr+8), w3=*(const float4*)(wr+12);
  float s=z0.x*w0.x;
  s=fmaf(z0.y,w0.y,s); s=fmaf(z0.z,w0.z,s); s=fmaf(z0.w,w0.w,s);
  s=fmaf(z1.x,w1.x,s); s=fmaf(z1.y,w1.y,s); s=fmaf(z1.z,w1.z,s); s=fmaf(z1.w,w1.w,s);
  s=fmaf(z2.x,w2.x,s); s=fmaf(z2.y,w2.y,s); s=fmaf(z2.z,w2.z,s); s=fmaf(z2.w,w2.w,s);
  s=fmaf(z3.x,w3.x,s); s=fmaf(z3.y,w3.y,s); s=fmaf(z3.z,w3.z,s); s=fmaf(z3.w,w3.w,s);
  #pragma unroll
  for(int o=8;o>=1;o>>=1) s+=__shfl_xor_sync(mask,s,o);
  return s;
}

// ===================== K1 (R15 verbatim) =====================
extern __shared__ float k1s[];
__global__ __launch_bounds__(256,1) void k1(const float* __restrict__ z,const float* __restrict__ pw){
  int tid=threadIdx.x, t=blockIdx.x;
  if(t<256){
    int pix0=t*128, b=pix0>>12, hw0=pix0&4095;
    const float* zb=z+(size_t)b*Cc*HWp+hw0;
    #pragma unroll
    for(int i=0;i<32;i++){
      int e4=tid+i*256; int c=e4>>5; int p4=(e4&31)<<2;
      float4 v=*(const float4*)(zb+(size_t)c*HWp+p4);
      float* d=k1s+c*129+p4;
      d[0]=v.x; d[1]=v.y; d[2]=v.z; d[3]=v.w;
    }
    __syncthreads();
    #pragma unroll 8
    for(int i=0;i<128;i++) g_zt[(size_t)(pix0+i)*Cc+tid]=k1s[tid*129+i];
    uint4* Ah=g_Af+(size_t)t*4096;
    #pragma unroll
    for(int i=0;i<16;i++){
      int u=tid+i*256;
      int lane=u&31, ks=(u>>5)&15, mt=u>>9;
      int r0=mt*16+(lane>>2);
      int c0=ks*16+((lane&3)<<1);
      u16 h0=h16(k1s[(c0  )*129+r0  ]*64.f), h1=h16(k1s[(c0+1)*129+r0  ]*64.f);
      u16 h2=h16(k1s[(c0  )*129+r0+8]*64.f), h3=h16(k1s[(c0+1)*129+r0+8]*64.f);
      u16 h4=h16(k1s[(c0+8)*129+r0  ]*64.f), h5=h16(k1s[(c0+9)*129+r0  ]*64.f);
      u16 h6=h16(k1s[(c0+8)*129+r0+8]*64.f), h7=h16(k1s[(c0+9)*129+r0+8]*64.f);
      uint4 H;
      H.x=h0|((u32)h1<<16); H.y=h2|((u32)h3<<16); H.z=h4|((u32)h5<<16); H.w=h6|((u32)h7<<16);
      Ah[u]=H;
    }
  } else {
    int base=(t-256)*2048;
    #pragma unroll
    for(int i=0;i<8;i++){
      int u=base+tid+i*256;
      int lane=u&31;
      int ks=(u>>5)&15;
      int nt=(u>>9)&15;
      int chunk=u>>13;
      int n=chunk*128+nt*8+(lane>>2);
      int k0=ks*16+((lane&3)<<1);
      const float* sp=pw+(size_t)n*Cc;
      u16 h0=h16(sp[k0  ]*32.f), h1=h16(sp[k0+1]*32.f);
      u16 h2=h16(sp[k0+8]*32.f), h3=h16(sp[k0+9]*32.f);
      g_Bh[(size_t)chunk*8192 + (nt*16+ks)*32 + lane]
        = (u64)(h0|((u32)h1<<16)) | ((u64)(h2|((u32)h3<<16))<<32);
    }
  }
}

// ===================== K2 (R15 + delta/rescore tweaks) =====================
// dyn smem: A hi 64KB [0,65536); B buf0 [65536,+65536); B buf1 [131072,+65536) = 196608
extern __shared__ char k2s[];
__global__ __launch_bounds__(512,1) void k2(const float* __restrict__ z,const float* __restrict__ pw,
                                            const float* __restrict__ pb,const float* __restrict__ emb,
                                            float* __restrict__ out){
  __shared__ u32 s_best[128];
  __shared__ float s_pb[1024];
  __shared__ int s_idx[128];
  __shared__ int s_cnt[128];
  __shared__ u16 s_cand[128][32];
  int tid=threadIdx.x, lane=tid&31, warp=tid>>5, mw=warp&3, nw=warp>>2, t=blockIdx.x;
  int pix0=t*128, b=pix0>>12, hw0=pix0&4095;
  char* sm=k2s;
  u32 smb=smem_u32(k2s);

  { const uint4* src=g_Af+(size_t)t*4096; uint4* dst=(uint4*)sm;
    #pragma unroll
    for(int i=0;i<8;i++) dst[tid+i*512]=src[tid+i*512]; }
  for(int i=tid;i<1024;i+=512) s_pb[i]=pb[i];
  if(tid<128){ s_best[tid]=0u; s_cnt[tid]=0; }
  __syncthreads();

  #pragma unroll
  for(int c2=0;c2<2;c2++){
    u32 d=smb+65536+c2*65536;
    const char* s=(const char*)g_Bh+(size_t)c2*65536;
    #pragma unroll
    for(int j2=0;j2<8;j2++){int e=tid+j2*512; cpa16(d+e*16,s+(size_t)e*16);}
    CPA_COMMIT();
  }

  float bestV[4], secV[4]; int bestI[4];
  #pragma unroll
  for(int i=0;i<4;i++){bestV[i]=-3.4e38f;secV[i]=-3.4e38f;bestI[i]=0;}
  const float inv=4.8828125e-4f;
  const uint4* Ahp=(const uint4*)sm;

  for(int nc=0;nc<8;nc++){
    CPA_WAIT1();
    __syncthreads();
    const char* Bst=sm+65536+(nc&1)*65536;
    float C[2][4][4];
    #pragma unroll
    for(int i=0;i<2;i++)
      #pragma unroll
      for(int j=0;j<4;j++)
        #pragma unroll
        for(int c=0;c<4;c++) C[i][j][c]=0.f;

    #pragma unroll
    for(int ks=0;ks<16;ks++){
      u32 ah[2][4];
      #pragma unroll
      for(int i=0;i<2;i++){
        uint4 va=Ahp[((mw*2+i)*16+ks)*32+lane];
        ah[i][0]=va.x; ah[i][1]=va.y; ah[i][2]=va.z; ah[i][3]=va.w;
      }
      u32 bh[4][2];
      #pragma unroll
      for(int j=0;j<4;j++){
        int nt=nw*4+j;
        uint2 vh=*(const uint2*)(Bst+(size_t)((nt*16+ks)*32+lane)*8);
        bh[j][0]=vh.x; bh[j][1]=vh.y;
      }
      #pragma unroll
      for(int i=0;i<2;i++)
        #pragma unroll
        for(int j=0;j<4;j++)
          hmma(C[i][j],ah[i],bh[j]);
    }

    int nb=nc*128+nw*32+((lane&3)<<1);
    #pragma unroll
    for(int i=0;i<2;i++)
      #pragma unroll
      for(int rr=0;rr<2;rr++){
        int r=i*2+rr;
        #pragma unroll
        for(int j=0;j<4;j++)
          #pragma unroll
          for(int cc=0;cc<2;cc++){
            int n=nb+j*8+cc;
            float val=C[i][j][rr*2+cc]*inv+s_pb[n];
            if(val>bestV[r]){secV[r]=bestV[r];bestV[r]=val;bestI[r]=n;}
            else if(val>secV[r]) secV[r]=val;
          }
      }
    __syncthreads();
    if(nc+2<8){
      u32 d=smb+65536+(nc&1)*65536;
      const char* s=(const char*)g_Bh+(size_t)(nc+2)*65536;
      #pragma unroll
      for(int j2=0;j2<8;j2++){int e=tid+j2*512; cpa16(d+e*16,s+(size_t)e*16);}
    }
    CPA_COMMIT();
  }
  CPA_WAIT0();

  #pragma unroll
  for(int i=0;i<2;i++)
    #pragma unroll
    for(int rr=0;rr<2;rr++){
      int row=mw*32+i*16+rr*8+(lane>>2);
      atomicMax(&s_best[row],ordu(bestV[i*2+rr]));
    }
  __syncthreads();

  #pragma unroll
  for(int i=0;i<2;i++)
    #pragma unroll
    for(int rr=0;rr<2;rr++){
      int r=i*2+rr;
      int row=mw*32+i*16+rr*8+(lane>>2);
      float thr=unord(s_best[row])-DELTA;
      if(bestV[r]>=thr){
        int slot=atomicAdd(&s_cnt[row],1);
        s_cand[row][slot]=(u16)bestI[r];
      }
      if(secV[r]>=thr){
        int slot=atomicAdd(&s_cnt[row],1);
        s_cand[row][slot]=(u16)(0x8000u|((u32)nw<<2)|(u32)(lane&3));
      }
    }
  __syncthreads();

  // exact rescore: HALF-warp per pixel (32 workers x 4 pixels)
  {
    int half=lane>>4, hl=lane&15;
    u32 hmask=half?0xFFFF0000u:0x0000FFFFu;
    int hw=warp*2+half;                       // 0..31
    for(int p=hw;p<128;p+=32){
      const float* zr=g_zt+(size_t)(pix0+p)*Cc+hl*16;
      float4 z0=*(const float4*)zr,      z1=*(const float4*)(zr+4);
      float4 z2=*(const float4*)(zr+8),  z3=*(const float4*)(zr+12);
      float bv=-3.4e38f; int bi=1024;
      int cnt=s_cnt[p];
      for(int e=0;e<cnt;e++){
        u32 ent=s_cand[p][e];
        if(ent<0x8000u){
          int n=(int)ent;
          float v=wdot16(z0,z1,z2,z3,pw,n,hl,hmask)+s_pb[n];
          if(v>bv||(v==bv&&n<bi)){bv=v;bi=n;}
        }else{
          int nwm=(int)((ent>>2)&3), q=(int)(ent&3);
          for(int nc2=0;nc2<8;nc2++)
            for(int j=0;j<4;j++)
              #pragma unroll
              for(int cc=0;cc<2;cc++){
                int n=nc2*128+nwm*32+j*8+q*2+cc;
                float v=wdot16(z0,z1,z2,z3,pw,n,hl,hmask)+s_pb[n];
                if(v>bv||(v==bv&&n<bi)){bv=v;bi=n;}
              }
        }
      }
      if(hl==0){ s_idx[p]=bi; out[IND_OFF+pix0+p]=(float)bi; }
    }
  }
  if(t==0&&tid==0) out[DIFF_OFF]=0.0f;
  __syncthreads();

  // gather epilogue (R15 verbatim)
  float* gs2=(float*)sm;           // [128][257] = 131584B < 196608
  for(int i=tid;i<8192;i+=512){
    int p=i>>6; int d4=(i&63)<<2;
    float4 v=*(const float4*)(emb+(size_t)s_idx[p]*Dd+d4);
    float* d=gs2+p*257+d4;
    d[0]=v.x; d[1]=v.y; d[2]=v.z; d[3]=v.w;
  }
  __syncthreads();
  float* outz=out+(size_t)b*Dd*HWp+hw0;
  for(int i=tid;i<32768;i+=512){
    int d=i>>7, p=i&127;
    outz[(size_t)d*HWp+p]=gs2[p*257+d];
  }
}

extern "C" void kernel_launch(void* const* d_in, const int* in_sizes, int n_in,
                              void* d_out, int out_size)
{
  const float* z  =(const float*)d_in[0];
  const float* pw =(const float*)d_in[1];
  const float* pb =(const float*)d_in[2];
  const float* emb=(const float*)d_in[3];
  float* out=(float*)d_out;
  cudaFuncSetAttribute(k1,cudaFuncAttributeMaxDynamicSharedMemorySize,132096);
  cudaFuncSetAttribute(k2,cudaFuncAttributeMaxDynamicSharedMemorySize,196608);
  k1<<<288,256,132096>>>(z,pw);
  k2<<<256,512,196608>>>(z,pw,pb,emb,out);
}